// round 4
// baseline (speedup 1.0000x reference)
#include <cuda_runtime.h>
#include <math_constants.h>
#include <cstdint>

#define POOL 7
#define NUM_ROIS 300
#define HH 50
#define WW 50
#define CC 512
#define NPIX (HH * WW)
#define NBINS (POOL * POOL)
#define VEC_PER_BIN (CC / 4)              // 128 float4 per bin
#define VEC_PER_ROI (NBINS * VEC_PER_BIN) // 6272 float4 per roi
#define ROI_BYTES (VEC_PER_ROI * 16)      // 98304 bytes

// Scratch: channel-max per pixel (10 KB). __device__ global (no allocation).
__device__ float g_fmax[NPIX];

// K1: one warp per pixel, reduce 512 contiguous fp32 -> 1 fp32.
__global__ void fmax_kernel(const float* __restrict__ fm) {
    int gwarp = (blockIdx.x * blockDim.x + threadIdx.x) >> 5;
    int lane  = threadIdx.x & 31;
    if (gwarp >= NPIX) return;
    const float4* p = reinterpret_cast<const float4*>(fm + (size_t)gwarp * CC);
    float m = -CUDART_INF_F;
#pragma unroll
    for (int i = 0; i < 4; i++) {
        float4 v = p[lane + i * 32];
        m = fmaxf(m, fmaxf(fmaxf(v.x, v.y), fmaxf(v.z, v.w)));
    }
#pragma unroll
    for (int s = 16; s; s >>= 1)
        m = fmaxf(m, __shfl_xor_sync(0xffffffffu, m, s));
    if (lane == 0) g_fmax[gwarp] = m;
}

// K2: one block per ROI. Build the 98KB broadcast tile in smem, then emit it
// with a single TMA bulk store (cp.async.bulk), bypassing the STG drain path.
__global__ void __launch_bounds__(256) roi_tma_kernel(
    const float* __restrict__ rois, float* __restrict__ out) {
    extern __shared__ float4 s_out[];       // 98304 bytes, 16B aligned
    __shared__ float s_fmax[NPIX];
    __shared__ float s_bin[NBINS];

    int roi = blockIdx.x;
    int tid = threadIdx.x;

    // Stage fmax plane into smem (coalesced, all L2 hits).
    for (int i = tid; i < NPIX; i += 256)
        s_fmax[i] = g_fmax[i];

    const float inv = 1.0f / 16.0f;
    int x1 = (int)(rois[roi * 5 + 1] * inv);
    int y1 = (int)(rois[roi * 5 + 2] * inv);
    int x2 = (int)(rois[roi * 5 + 3] * inv);
    int y2 = (int)(rois[roi * 5 + 4] * inv);
    int rh = y2 - y1 + 1;
    int rw = x2 - x1 + 1;
    __syncthreads();

    // 49 threads compute the bin maxes from smem.
    if (tid < NBINS) {
        int bi = tid / POOL;
        int bj = tid - bi * POOL;
        int hs = min(max(y1 + (bi * rh) / POOL, 0), HH);
        int he = min(max(y1 + ((bi + 1) * rh + POOL - 1) / POOL, 0), HH);
        int ws = min(max(x1 + (bj * rw) / POOL, 0), WW);
        int we = min(max(x1 + ((bj + 1) * rw + POOL - 1) / POOL, 0), WW);
        float m = -CUDART_INF_F;
        for (int r = hs; r < he; r++)
            for (int c = ws; c < we; c++)
                m = fmaxf(m, s_fmax[r * WW + c]);
        s_bin[tid] = m;
    }
    __syncthreads();

    // Fill the 98KB output tile in smem (STS.128, ~25 iters/thread).
#pragma unroll 4
    for (int i = tid; i < VEC_PER_ROI; i += 256) {
        float v = s_bin[i >> 7];
        s_out[i] = make_float4(v, v, v, v);
    }
    __syncthreads();

    // One thread emits the whole tile with a bulk async store.
    if (tid == 0) {
        asm volatile("fence.proxy.async.shared::cta;" ::: "memory");
        uint32_t saddr;
        asm("{ .reg .u64 t; cvta.to.shared.u64 t, %1; cvt.u32.u64 %0, t; }"
            : "=r"(saddr) : "l"(s_out));
        char* gdst = reinterpret_cast<char*>(out) + (size_t)roi * ROI_BYTES;
        asm volatile(
            "cp.async.bulk.global.shared::cta.bulk_group [%0], [%1], %2;"
            :: "l"(gdst), "r"(saddr), "r"((uint32_t)ROI_BYTES) : "memory");
        asm volatile("cp.async.bulk.commit_group;" ::: "memory");
        asm volatile("cp.async.bulk.wait_group 0;" ::: "memory");
    }
}

extern "C" void kernel_launch(void* const* d_in, const int* in_sizes, int n_in,
                              void* d_out, int out_size) {
    const float* rois = (const float*)d_in[0];
    const float* fm   = (const float*)d_in[1];
    if (in_sizes[0] != NUM_ROIS * 5) {
        const float* t = rois; rois = fm; fm = t;
    }
    float* out = (float*)d_out;

    // Allow 96KB+ dynamic smem (idempotent; not a stream op, capture-safe).
    static bool attr_set = false;
    if (!attr_set) {
        cudaFuncSetAttribute(roi_tma_kernel,
                             cudaFuncAttributeMaxDynamicSharedMemorySize,
                             ROI_BYTES);
        attr_set = true;
    }

    int threads1 = 256;
    int blocks1  = (NPIX * 32 + threads1 - 1) / threads1;
    fmax_kernel<<<blocks1, threads1>>>(fm);

    roi_tma_kernel<<<NUM_ROIS, 256, ROI_BYTES>>>(rois, out);
}

// round 5
// speedup vs baseline: 1.0711x; 1.0711x over previous
#include <cuda_runtime.h>
#include <math_constants.h>
#include <cstdint>

#define POOL 7
#define NUM_ROIS 300
#define HH 50
#define WW 50
#define CC 512
#define NPIX (HH * WW)
#define NBINS (POOL * POOL)
#define VEC_PER_BIN (CC / 4)              // 128 float4 per bin
#define VEC_PER_ROI (NBINS * VEC_PER_BIN) // 6272 float4 per roi
#define GRID 300
#define WARPS_TOTAL (GRID * 8)

// Scratch (no allocation): channel-max per pixel + barrier counters.
__device__ float g_fmax[NPIX];
__device__ unsigned g_bar_in;
__device__ unsigned g_bar_out;

__global__ void __launch_bounds__(256) roi_fused_kernel(
    const float* __restrict__ rois,
    const float* __restrict__ fm,
    float* __restrict__ out) {
    __shared__ float s_fmax[NPIX];
    __shared__ float s_bin[NBINS];

    int tid  = threadIdx.x;
    int roi  = blockIdx.x;
    int lane = tid & 31;
    int gw   = (blockIdx.x * 256 + tid) >> 5;   // global warp id, 0..2399

    // ---- Phase 1: channel-max per pixel (warp per pixel, grid-strided) ----
    for (int p = gw; p < NPIX; p += WARPS_TOTAL) {
        const float4* fp = reinterpret_cast<const float4*>(fm + (size_t)p * CC);
        float m = -CUDART_INF_F;
#pragma unroll
        for (int i = 0; i < 4; i++) {
            float4 v = fp[lane + i * 32];       // coalesced 128B/warp/iter
            m = fmaxf(m, fmaxf(fmaxf(v.x, v.y), fmaxf(v.z, v.w)));
        }
#pragma unroll
        for (int s = 16; s; s >>= 1)
            m = fmaxf(m, __shfl_xor_sync(0xffffffffu, m, s));
        if (lane == 0) g_fmax[p] = m;
    }
    __threadfence();
    __syncthreads();

    // ---- Device-wide barrier (all 300 blocks co-resident) ----
    if (tid == 0) {
        atomicAdd(&g_bar_in, 1u);
        while (atomicAdd(&g_bar_in, 0u) < (unsigned)GRID)
            __nanosleep(64);
    }
    __syncthreads();

    // ---- Phase 2: stage fmax, compute this ROI's 49 bin maxes ----
    for (int i = tid; i < NPIX; i += 256)
        s_fmax[i] = g_fmax[i];

    const float inv = 1.0f / 16.0f;
    int x1 = (int)(rois[roi * 5 + 1] * inv);
    int y1 = (int)(rois[roi * 5 + 2] * inv);
    int x2 = (int)(rois[roi * 5 + 3] * inv);
    int y2 = (int)(rois[roi * 5 + 4] * inv);
    int rh = y2 - y1 + 1;
    int rw = x2 - x1 + 1;
    __syncthreads();

    if (tid < NBINS) {
        int bi = tid / POOL;
        int bj = tid - bi * POOL;
        int hs = min(max(y1 + (bi * rh) / POOL, 0), HH);
        int he = min(max(y1 + ((bi + 1) * rh + POOL - 1) / POOL, 0), HH);
        int ws = min(max(x1 + (bj * rw) / POOL, 0), WW);
        int we = min(max(x1 + ((bj + 1) * rw + POOL - 1) / POOL, 0), WW);
        float m = -CUDART_INF_F;
        for (int r = hs; r < he; r++)
            for (int c = ws; c < we; c++)
                m = fmaxf(m, s_fmax[r * WW + c]);
        s_bin[tid] = m;
    }
    __syncthreads();

    // ---- Phase 3: stream 98KB of broadcast output (at the L2 write wall) ----
    float4* out4 = reinterpret_cast<float4*>(out) + (size_t)roi * VEC_PER_ROI;
#pragma unroll 4
    for (int i = tid; i < VEC_PER_ROI; i += 256) {
        float v = s_bin[i >> 7];
        out4[i] = make_float4(v, v, v, v);
    }

    // ---- Barrier counter reset for graph replays (last block out) ----
    if (tid == 0) {
        unsigned t = atomicAdd(&g_bar_out, 1u);
        if (t == (unsigned)(GRID - 1)) {
            atomicExch(&g_bar_in, 0u);
            atomicExch(&g_bar_out, 0u);
        }
    }
}

extern "C" void kernel_launch(void* const* d_in, const int* in_sizes, int n_in,
                              void* d_out, int out_size) {
    const float* rois = (const float*)d_in[0];
    const float* fm   = (const float*)d_in[1];
    if (in_sizes[0] != NUM_ROIS * 5) {
        const float* t = rois; rois = fm; fm = t;
    }
    float* out = (float*)d_out;

    roi_fused_kernel<<<GRID, 256>>>(rois, fm, out);
}